// round 15
// baseline (speedup 1.0000x reference)
#include <cuda_runtime.h>
#include <cstdint>

#define B_ 8
#define N_ 16384
#define M_ 1024
#define C_ 64
#define NS_ 32
#define COUT_ 67
#define R2_ 0.04f

#define FEAT_BLOCKS (B_ * C_)   // 512
#define XYZ_BLOCKS  (B_ * 3)    // 24
#define GD_SMEM ((N_ + M_) * 4) // 69632 bytes
#define BQT 512                 // ball-query tile points
#define NTILE (N_ / BQT)        // 32

// Scratch: ball-query indices (1 MB).
__device__ int g_idx[(size_t)B_ * M_ * NS_];

// ---------------------------------------------------------------------------
// Kernel 1: ball query — EXACT R14 form (unchanged for controlled profiling).
// ---------------------------------------------------------------------------
__global__ void __launch_bounds__(128) ballquery_kernel(
    const float* __restrict__ xyz, const float* __restrict__ new_xyz) {
    __shared__ float4 sp[2][BQT];        // 16 KB
    __shared__ int    sidx[4][NS_];
    __shared__ int    s_done;

    const int tid  = threadIdx.x;
    const int w    = tid >> 5;
    const int lane = tid & 31;
    const int q    = blockIdx.x * 4 + w;
    const int b    = q >> 10;

    const float4* src4 = (const float4*)(xyz + (size_t)b * N_ * 3);
    const float*  qp   = new_xyz + (size_t)q * 3;
    const float qx = qp[0], qy = qp[1], qz = qp[2];
    const unsigned ltm = (1u << lane) - 1u;

    if (tid == 0) s_done = 0;

    float4 ra, rb, rc;
    {
        const int fb = 3 * tid;
        ra = src4[fb]; rb = src4[fb + 1]; rc = src4[fb + 2];
        sp[0][4 * tid + 0] = make_float4(ra.x, ra.y, ra.z, 0.f);
        sp[0][4 * tid + 1] = make_float4(ra.w, rb.x, rb.y, 0.f);
        sp[0][4 * tid + 2] = make_float4(rb.z, rb.w, rc.x, 0.f);
        sp[0][4 * tid + 3] = make_float4(rc.y, rc.z, rc.w, 0.f);
    }
    __syncthreads();

    int  total   = 0;
    bool done    = false;
    bool counted = false;

    for (int t = 0; t < NTILE; t++) {
        const bool more = (t + 1) < NTILE;
        if (more) {
            const int fb = 384 * (t + 1) + 3 * tid;
            ra = src4[fb]; rb = src4[fb + 1]; rc = src4[fb + 2];
        }

        if (!done) {
            const float4* tp = sp[t & 1];
#pragma unroll
            for (int ch = 0; ch < 2; ch++) {
                unsigned m = 0u;
#pragma unroll
                for (int j = 0; j < 8; j++) {
                    const float4 p = tp[ch * 256 + j * 32 + lane];
                    const float dx = p.x - qx, dy = p.y - qy, dz = p.z - qz;
                    if (dx * dx + dy * dy + dz * dz < R2_) m |= 1u << j;
                }
                if (__ballot_sync(0xffffffffu, m != 0u)) {
                    int run = total;
#pragma unroll
                    for (int j = 0; j < 8; j++) {
                        const unsigned bm =
                            __ballot_sync(0xffffffffu, (m >> j) & 1u);
                        if (bm) {
                            const int pos = run + __popc(bm & ltm);
                            if (((m >> j) & 1u) && pos < NS_)
                                sidx[w][pos] =
                                    BQT * t + 256 * ch + 32 * j + lane;
                            run += __popc(bm);
                        }
                    }
                    total = run;
                    if (total >= NS_) { done = true; break; }
                }
            }
            if (done && !counted) {
                counted = true;
                if (lane == 0) atomicAdd(&s_done, 1);
            }
        }

        if (more) {
            sp[(t + 1) & 1][4 * tid + 0] = make_float4(ra.x, ra.y, ra.z, 0.f);
            sp[(t + 1) & 1][4 * tid + 1] = make_float4(ra.w, rb.x, rb.y, 0.f);
            sp[(t + 1) & 1][4 * tid + 2] = make_float4(rb.z, rb.w, rc.x, 0.f);
            sp[(t + 1) & 1][4 * tid + 3] = make_float4(rc.y, rc.z, rc.w, 0.f);
        }
        __syncthreads();
        if (s_done == 4) break;
    }

    __syncwarp();
    int v;
    if (total == 0) {
        v = N_ - 1;  // reference: all-invalid -> clamped gather
    } else {
        const int first = sidx[w][0];
        v = (lane < min(total, NS_)) ? sidx[w][lane] : first;
    }
    g_idx[(size_t)q * NS_ + lane] = v;
}

// ---------------------------------------------------------------------------
// Kernel 2: direct grouping — EXACT R11/R14 form (measured best, 28.1us).
// ---------------------------------------------------------------------------
__global__ void __launch_bounds__(512) group_direct_kernel(
    const float* __restrict__ xyz, const float* __restrict__ new_xyz,
    const float* __restrict__ feats, float* __restrict__ out) {
    extern __shared__ float row[];           // [N_] (+ [M_] for xyz path)
    const int blk = blockIdx.x;
    const int t   = threadIdx.x;

    if (blk < FEAT_BLOCKS) {
        const int b = blk >> 6;
        const int c = blk & 63;

        const float4* src = (const float4*)(feats + ((size_t)b * C_ + c) * N_);
        float4* row4 = (float4*)row;
#pragma unroll
        for (int i = 0; i < 8; i++)
            row4[t + i * 512] = src[t + i * 512];
        __syncthreads();

        const int4* ib4 = (const int4*)(g_idx + (size_t)b * M_ * NS_);
        float4* ob4 = (float4*)(out + ((size_t)b * COUT_ + 3 + c) * (M_ * NS_));
#pragma unroll
        for (int e0 = 0; e0 < 4; e0++) {
            int4 id[4];
#pragma unroll
            for (int j = 0; j < 4; j++)
                id[j] = ib4[t + (e0 * 4 + j) * 512];
#pragma unroll
            for (int j = 0; j < 4; j++) {
                float4 v;
                v.x = row[id[j].x]; v.y = row[id[j].y];
                v.z = row[id[j].z]; v.w = row[id[j].w];
                ob4[t + (e0 * 4 + j) * 512] = v;
            }
        }
    } else {
        const int blk2 = blk - FEAT_BLOCKS;
        const int b = blk2 / 3;
        const int c = blk2 % 3;
        float* nq = row + N_;

        for (int i = t; i < N_; i += 512)
            row[i] = xyz[(size_t)b * N_ * 3 + (size_t)i * 3 + c];
        for (int i = t; i < M_; i += 512)
            nq[i] = new_xyz[(size_t)b * M_ * 3 + (size_t)i * 3 + c];
        __syncthreads();

        const int4* ib4 = (const int4*)(g_idx + (size_t)b * M_ * NS_);
        float4* ob4 = (float4*)(out + ((size_t)b * COUT_ + c) * (M_ * NS_));
#pragma unroll
        for (int e0 = 0; e0 < 4; e0++) {
            int4 id[4];
#pragma unroll
            for (int j = 0; j < 4; j++)
                id[j] = ib4[t + (e0 * 4 + j) * 512];
#pragma unroll
            for (int j = 0; j < 4; j++) {
                const int i4 = t + (e0 * 4 + j) * 512;
                const float qv = nq[i4 >> 3];
                float4 v;
                v.x = row[id[j].x] - qv; v.y = row[id[j].y] - qv;
                v.z = row[id[j].z] - qv; v.w = row[id[j].w] - qv;
                ob4[i4] = v;
            }
        }
    }
}

// ---------------------------------------------------------------------------
// No-op kernel: pads each kernel_launch call to 5 launches so ncu's
// "-s 5 -c 1" capture (launch #6 == position 1 mod 5) lands on
// ballquery_kernel instead of always group_direct_kernel. Deterministic,
// writes nothing.
// ---------------------------------------------------------------------------
__global__ void nop_kernel() {}

// ---------------------------------------------------------------------------
extern "C" void kernel_launch(void* const* d_in, const int* in_sizes, int n_in,
                              void* d_out, int out_size) {
    const float* xyz = nullptr;
    const float* new_xyz = nullptr;
    const float* feats = nullptr;
    for (int i = 0; i < n_in; i++) {
        if (in_sizes[i] == B_ * N_ * 3)      xyz     = (const float*)d_in[i];
        else if (in_sizes[i] == B_ * M_ * 3) new_xyz = (const float*)d_in[i];
        else if (in_sizes[i] == B_ * C_ * N_) feats  = (const float*)d_in[i];
    }
    float* out = (float*)d_out;

    cudaFuncSetAttribute(group_direct_kernel,
                         cudaFuncAttributeMaxDynamicSharedMemorySize, GD_SMEM);

    ballquery_kernel<<<(B_ * M_) / 4, 128>>>(xyz, new_xyz);
    group_direct_kernel<<<FEAT_BLOCKS + XYZ_BLOCKS, 512, GD_SMEM>>>(
        xyz, new_xyz, feats, out);
    nop_kernel<<<1, 32>>>();
    nop_kernel<<<1, 32>>>();
    nop_kernel<<<1, 32>>>();
}

// round 17
// speedup vs baseline: 1.1110x; 1.1110x over previous
#include <cuda_runtime.h>
#include <cstdint>

#define B_ 8
#define N_ 16384
#define M_ 1024
#define C_ 64
#define NS_ 32
#define COUT_ 67
#define R2_ 0.04f

#define PAIR_BLOCKS (B_ * C_ / 2)  // 256 (2 channels per block)
#define XYZ_BLOCKS  (B_ * 3)       // 24
#define GD_SMEM (N_ * 8)           // 131072 bytes (float2 row; xyz path uses less)
#define BQT 512                    // ball-query tile points
#define NTILE (N_ / BQT)           // 32

// Scratch: ball-query indices (1 MB).
__device__ int g_idx[(size_t)B_ * M_ * NS_];

// ---------------------------------------------------------------------------
// Kernel 1: ball query — EXACT R14 form (measured plateau; unchanged).
// ---------------------------------------------------------------------------
__global__ void __launch_bounds__(128) ballquery_kernel(
    const float* __restrict__ xyz, const float* __restrict__ new_xyz) {
    __shared__ float4 sp[2][BQT];        // 16 KB
    __shared__ int    sidx[4][NS_];
    __shared__ int    s_done;

    const int tid  = threadIdx.x;
    const int w    = tid >> 5;
    const int lane = tid & 31;
    const int q    = blockIdx.x * 4 + w;
    const int b    = q >> 10;

    const float4* src4 = (const float4*)(xyz + (size_t)b * N_ * 3);
    const float*  qp   = new_xyz + (size_t)q * 3;
    const float qx = qp[0], qy = qp[1], qz = qp[2];
    const unsigned ltm = (1u << lane) - 1u;

    if (tid == 0) s_done = 0;

    float4 ra, rb, rc;
    {
        const int fb = 3 * tid;
        ra = src4[fb]; rb = src4[fb + 1]; rc = src4[fb + 2];
        sp[0][4 * tid + 0] = make_float4(ra.x, ra.y, ra.z, 0.f);
        sp[0][4 * tid + 1] = make_float4(ra.w, rb.x, rb.y, 0.f);
        sp[0][4 * tid + 2] = make_float4(rb.z, rb.w, rc.x, 0.f);
        sp[0][4 * tid + 3] = make_float4(rc.y, rc.z, rc.w, 0.f);
    }
    __syncthreads();

    int  total   = 0;
    bool done    = false;
    bool counted = false;

    for (int t = 0; t < NTILE; t++) {
        const bool more = (t + 1) < NTILE;
        if (more) {
            const int fb = 384 * (t + 1) + 3 * tid;
            ra = src4[fb]; rb = src4[fb + 1]; rc = src4[fb + 2];
        }

        if (!done) {
            const float4* tp = sp[t & 1];
#pragma unroll
            for (int ch = 0; ch < 2; ch++) {
                unsigned m = 0u;
#pragma unroll
                for (int j = 0; j < 8; j++) {
                    const float4 p = tp[ch * 256 + j * 32 + lane];
                    const float dx = p.x - qx, dy = p.y - qy, dz = p.z - qz;
                    if (dx * dx + dy * dy + dz * dz < R2_) m |= 1u << j;
                }
                if (__ballot_sync(0xffffffffu, m != 0u)) {
                    int run = total;
#pragma unroll
                    for (int j = 0; j < 8; j++) {
                        const unsigned bm =
                            __ballot_sync(0xffffffffu, (m >> j) & 1u);
                        if (bm) {
                            const int pos = run + __popc(bm & ltm);
                            if (((m >> j) & 1u) && pos < NS_)
                                sidx[w][pos] =
                                    BQT * t + 256 * ch + 32 * j + lane;
                            run += __popc(bm);
                        }
                    }
                    total = run;
                    if (total >= NS_) { done = true; break; }
                }
            }
            if (done && !counted) {
                counted = true;
                if (lane == 0) atomicAdd(&s_done, 1);
            }
        }

        if (more) {
            sp[(t + 1) & 1][4 * tid + 0] = make_float4(ra.x, ra.y, ra.z, 0.f);
            sp[(t + 1) & 1][4 * tid + 1] = make_float4(ra.w, rb.x, rb.y, 0.f);
            sp[(t + 1) & 1][4 * tid + 2] = make_float4(rb.z, rb.w, rc.x, 0.f);
            sp[(t + 1) & 1][4 * tid + 3] = make_float4(rc.y, rc.z, rc.w, 0.f);
        }
        __syncthreads();
        if (s_done == 4) break;
    }

    __syncwarp();
    int v;
    if (total == 0) {
        v = N_ - 1;  // reference: all-invalid -> clamped gather
    } else {
        const int first = sidx[w][0];
        v = (lane < min(total, NS_)) ? sidx[w][lane] : first;
    }
    g_idx[(size_t)q * NS_ + lane] = v;
}

// ---------------------------------------------------------------------------
// Kernel 2: direct grouping, 2 channels per block (crossbar fix).
// row2[n] = {feats[c0][n], feats[c0+1][n]} in 128KB smem: one LDS.64 feeds
// TWO output channels -> gather LDS instructions and conflict-cycles halved,
// idx LDG traffic halved, 280 total blocks. Store path unchanged (STG.128).
// ---------------------------------------------------------------------------
__global__ void __launch_bounds__(512) group_direct_kernel(
    const float* __restrict__ xyz, const float* __restrict__ new_xyz,
    const float* __restrict__ feats, float* __restrict__ out) {
    extern __shared__ float row[];           // float2[N_] | (float[N_]+float[M_])
    const int blk = blockIdx.x;
    const int t   = threadIdx.x;

    if (blk < PAIR_BLOCKS) {
        const int b  = blk >> 5;             // 32 pairs per batch
        const int p  = blk & 31;
        const int c0 = p * 2;

        const float* src0 = feats + ((size_t)b * C_ + c0) * N_;
        const float* src1 = src0 + N_;
        float2* row2 = (float2*)row;
#pragma unroll
        for (int i = 0; i < 32; i++) {
            const int n = t + i * 512;
            row2[n] = make_float2(src0[n], src1[n]);
        }
        __syncthreads();

        const int4* ib4 = (const int4*)(g_idx + (size_t)b * M_ * NS_);
        float4* ob0 = (float4*)(out + ((size_t)b * COUT_ + 3 + c0) * (M_ * NS_));
        float4* ob1 = (float4*)(out + ((size_t)b * COUT_ + 4 + c0) * (M_ * NS_));
#pragma unroll
        for (int e0 = 0; e0 < 4; e0++) {
            int4 id[4];
#pragma unroll
            for (int j = 0; j < 4; j++)
                id[j] = ib4[t + (e0 * 4 + j) * 512];
#pragma unroll
            for (int j = 0; j < 4; j++) {
                const float2 a = row2[id[j].x];
                const float2 bb = row2[id[j].y];
                const float2 c = row2[id[j].z];
                const float2 d = row2[id[j].w];
                const int i4 = t + (e0 * 4 + j) * 512;
                ob0[i4] = make_float4(a.x, bb.x, c.x, d.x);
                ob1[i4] = make_float4(a.y, bb.y, c.y, d.y);
            }
        }
    } else {
        const int blk2 = blk - PAIR_BLOCKS;
        const int b = blk2 / 3;
        const int c = blk2 % 3;
        float* nq = row + N_;

        for (int i = t; i < N_; i += 512)
            row[i] = xyz[(size_t)b * N_ * 3 + (size_t)i * 3 + c];
        for (int i = t; i < M_; i += 512)
            nq[i] = new_xyz[(size_t)b * M_ * 3 + (size_t)i * 3 + c];
        __syncthreads();

        const int4* ib4 = (const int4*)(g_idx + (size_t)b * M_ * NS_);
        float4* ob4 = (float4*)(out + ((size_t)b * COUT_ + c) * (M_ * NS_));
#pragma unroll
        for (int e0 = 0; e0 < 4; e0++) {
            int4 id[4];
#pragma unroll
            for (int j = 0; j < 4; j++)
                id[j] = ib4[t + (e0 * 4 + j) * 512];
#pragma unroll
            for (int j = 0; j < 4; j++) {
                const int i4 = t + (e0 * 4 + j) * 512;
                const float qv = nq[i4 >> 3];
                float4 v;
                v.x = row[id[j].x] - qv; v.y = row[id[j].y] - qv;
                v.z = row[id[j].z] - qv; v.w = row[id[j].w] - qv;
                ob4[i4] = v;
            }
        }
    }
}

// ---------------------------------------------------------------------------
extern "C" void kernel_launch(void* const* d_in, const int* in_sizes, int n_in,
                              void* d_out, int out_size) {
    const float* xyz = nullptr;
    const float* new_xyz = nullptr;
    const float* feats = nullptr;
    for (int i = 0; i < n_in; i++) {
        if (in_sizes[i] == B_ * N_ * 3)      xyz     = (const float*)d_in[i];
        else if (in_sizes[i] == B_ * M_ * 3) new_xyz = (const float*)d_in[i];
        else if (in_sizes[i] == B_ * C_ * N_) feats  = (const float*)d_in[i];
    }
    float* out = (float*)d_out;

    cudaFuncSetAttribute(group_direct_kernel,
                         cudaFuncAttributeMaxDynamicSharedMemorySize, GD_SMEM);

    ballquery_kernel<<<(B_ * M_) / 4, 128>>>(xyz, new_xyz);
    group_direct_kernel<<<PAIR_BLOCKS + XYZ_BLOCKS, 512, GD_SMEM>>>(
        xyz, new_xyz, feats, out);
}